// round 8
// baseline (speedup 1.0000x reference)
#include <cuda_runtime.h>

// Lifting wavelet forward transform, v8: v3 body (best kernel, 37.5us: LDC taps,
// 32 regs, occ 84%) with the __constant__ taps written by a tiny SETUP KERNEL
// instead of cudaMemcpyToSymbolAsync graph nodes (which cost ~8-10us total).
// __constant__ symbols are module global memory; a kernel may STG through the
// symbol's device address. Constant cache is invalidated at launch boundaries,
// and taps are identical across graph replays, so coherence is benign.
//
// input: (4096, 8192) f32. even = in[:, ::2], odd = in[:, 1::2] (4096 each).
// wavelet[j] = scaling_rec[7-j] * (j odd ? -1 : +1)
// odd_out[k]  = odd[k]  - sum_j wavelet[j] * even[(k-j) mod 4096]
// even_out[k] = even[k] - sum_j scaling[j] * odd[(k-j) mod 4096]
// Output: [even_updated | odd_updated], each 4096x4096 f32.

#define ROWS    4096
#define ROWLEN  8192
#define HALF    4096
#define NTH     256
#define FMASK   (ROWLEN - 1)

// [0..7] = wavelet taps (reversed + sign-flipped), [8..15] = scaling taps.
__constant__ float cTaps[16];

__global__ void wavelet_setup(const float* __restrict__ scaling,
                              const float* __restrict__ scaling_rec,
                              float* __restrict__ taps_dst)
{
    int t = threadIdx.x;           // 8 threads
    if (t < 8) {
        float w = scaling_rec[7 - t];
        taps_dst[t]     = (t & 1) ? -w : w;   // wavelet[j]
        taps_dst[8 + t] = scaling[t];
    }
}

__global__ __launch_bounds__(NTH)
void wavelet_fwd_v8(const float* __restrict__ in,
                    float* __restrict__ out)
{
    const int g   = blockIdx.x * NTH + threadIdx.x;  // 0 .. 4M-1
    const int row = g >> 10;                          // 1024 threads per row
    const int lk  = (g & 1023) << 2;                  // pair base: 0..4092

    const float* rowp = in + (size_t)row * ROWLEN;

    // Window: input floats (2*lk - 16 + i) mod 8192, i = 0..23.
    // 6 aligned float4 loads, circular via & FMASK. Front-batched -> MLP=6.
    float wnd[24];
#pragma unroll
    for (int q = 0; q < 6; q++) {
        int fi = (2 * lk - 16 + 4 * q) & FMASK;
        float4 v = *reinterpret_cast<const float4*>(rowp + fi);
        wnd[4*q+0] = v.x; wnd[4*q+1] = v.y; wnd[4*q+2] = v.z; wnd[4*q+3] = v.w;
    }

    // Taps via LDC (constant cache): ptxas rematerializes freely, no pinned regs.
    const float w0 = cTaps[0], w1 = cTaps[1], w2 = cTaps[2], w3 = cTaps[3];
    const float w4 = cTaps[4], w5 = cTaps[5], w6 = cTaps[6], w7 = cTaps[7];
    const float c0 = cTaps[8],  c1 = cTaps[9],  c2 = cTaps[10], c3 = cTaps[11];
    const float c4 = cTaps[12], c5 = cTaps[13], c6 = cTaps[14], c7 = cTaps[15];

    // Pair (lk+m): even = wnd[2m+16], odd = wnd[2m+17].
    float rE[4], rO[4];
#pragma unroll
    for (int m = 0; m < 4; m++) {
        const int b = 2 * m + 16;
        float e8 = wnd[b], o8 = wnd[b + 1];
        float ce = w0*e8
                 + w1*wnd[b-2]  + w2*wnd[b-4]  + w3*wnd[b-6]
                 + w4*wnd[b-8]  + w5*wnd[b-10] + w6*wnd[b-12]
                 + w7*wnd[b-14];
        float co = c0*o8
                 + c1*wnd[b-1]  + c2*wnd[b-3]  + c3*wnd[b-5]
                 + c4*wnd[b-7]  + c5*wnd[b-9]  + c6*wnd[b-11]
                 + c7*wnd[b-13];
        rO[m] = o8 - ce;   // odd  - conv(even, wavelet)
        rE[m] = e8 - co;   // even - conv(odd,  scaling)
    }

    const size_t obase = (size_t)row * HALF + lk;
    *reinterpret_cast<float4*>(out + obase) =
        make_float4(rE[0], rE[1], rE[2], rE[3]);
    *reinterpret_cast<float4*>(out + (size_t)ROWS * HALF + obase) =
        make_float4(rO[0], rO[1], rO[2], rO[3]);
}

extern "C" void kernel_launch(void* const* d_in, const int* in_sizes, int n_in,
                              void* d_out, int out_size)
{
    const float* input       = (const float*)d_in[0];
    const float* scaling     = (const float*)d_in[1];
    const float* scaling_rec = (const float*)d_in[2];
    float* out = (float*)d_out;

    // Device address of the __constant__ symbol (host query; no allocation).
    float* taps_dst = nullptr;
    cudaGetSymbolAddress((void**)&taps_dst, cTaps);

    wavelet_setup<<<1, 32>>>(scaling, scaling_rec, taps_dst);

    const int total_threads = ROWS * (HALF / 4);       // 4M
    wavelet_fwd_v8<<<total_threads / NTH, NTH>>>(input, out);
}